// round 2
// baseline (speedup 1.0000x reference)
#include <cuda_runtime.h>
#include <math.h>

#define BB 8
#define CC 64
#define HH 256
#define WW 256
#define M1 20
#define M2 20
#define NL 4
#define HW 65536
#define NPIX (BB*HH*WW)   // 524288

// ---------------- static device scratch (no allocation allowed) ----------------
__device__ float  g_bufA[BB*CC*HW];          // 134 MB
__device__ float  g_bufB[BB*CC*HW];          // 134 MB
__device__ float2 g_yw [BB*CC*HH*M2];        // DFT along W   (b,c,h,ky)
__device__ float2 g_xft[BB*CC*2*M1*M2];      // truncated spectrum (b,c,kxi,ky), kxi in [0,40)
__device__ float2 g_oft[BB*CC*2*M1*M2];      // after mode mixing
__device__ float2 g_zh [BB*CC*HH*M2];        // inverse DFT along H (b,o,h,ky)
__device__ float  g_wm [NL*CC*CC*9];         // merged 3x3 weights
__device__ float  g_bm [NL*CC];              // merged biases
__device__ float  g_tc [256];                // cos(2*pi*t/256)
__device__ float  g_ts [256];                // sin(2*pi*t/256)

__device__ __forceinline__ float* selbuf(int s){ return s ? g_bufB : g_bufA; }

__device__ __forceinline__ float gelu_exact(float x){
    return 0.5f * x * (1.0f + erff(x * 0.7071067811865476f));
}

// ---------------- twiddle init (double precision for accuracy) ----------------
__global__ void k_init_tw(){
    int i = threadIdx.x;
    double th = 6.283185307179586476925286766559 * (double)i / 256.0;
    g_tc[i] = (float)cos(th);
    g_ts[i] = (float)sin(th);
}

// ---------------- merge convh + convw + pw into one 3x3 conv ----------------
__global__ void k_merge(const float* __restrict__ ch, const float* __restrict__ cw,
                        const float* __restrict__ pw, const float* __restrict__ bh,
                        const float* __restrict__ bw, const float* __restrict__ bp){
    int idx = blockIdx.x * 256 + threadIdx.x;
    const int total = NL*CC*CC*9;
    if (idx < total){
        float v = ch[idx] + cw[idx];
        if ((idx % 9) == 4) v += pw[idx / 9];
        g_wm[idx] = v;
    }
    if (idx < NL*CC) g_bm[idx] = bh[idx] + bw[idx] + bp[idx];
}

// ---------------- fc0 lift: (B,H,W,3) -> (B,C,H,W) ----------------
__global__ void k_fc0(const float* __restrict__ x, const float* __restrict__ w,
                      const float* __restrict__ bias){
    __shared__ float sw[3*CC];
    __shared__ float sb[CC];
    int tid = threadIdx.x;
    if (tid < 3*CC) sw[tid] = w[tid];
    if (tid < CC)   sb[tid] = bias[tid];
    __syncthreads();
    int pix = blockIdx.x * 256 + tid;
    int b  = pix >> 16;
    int hw = pix & 65535;
    float x0 = x[pix*3+0], x1 = x[pix*3+1], x2 = x[pix*3+2];
    float* out = selbuf(0);
    #pragma unroll 8
    for (int c = 0; c < CC; c++){
        float v = x0*sw[c] + x1*sw[64+c] + x2*sw[128+c] + sb[c];
        out[((b*CC + c) << 16) + hw] = v;
    }
}

// ---------------- forward DFT along W: 256 -> 20 modes ----------------
__global__ void k_dftw(int insel){
    __shared__ float srow[8][WW];
    __shared__ float stc[256], sts[256];
    int tid = threadIdx.x;     // 256
    int hg  = blockIdx.x;      // 0..31 (groups of 8 rows)
    int c   = blockIdx.y;
    int b   = blockIdx.z;
    stc[tid] = g_tc[tid]; sts[tid] = g_ts[tid];
    const float* in = selbuf(insel) + ((b*CC + c) << 16) + hg*8*WW;
    #pragma unroll
    for (int r = 0; r < 8; r++) srow[r][tid] = in[r*WW + tid];
    __syncthreads();
    if (tid < 160){
        int r = tid / 20, ky = tid % 20;
        float re = 0.f, im = 0.f;
        int idx = 0;
        #pragma unroll 4
        for (int w = 0; w < WW; w++){
            float v = srow[r][w];
            re += v * stc[idx];
            im -= v * sts[idx];
            idx = (idx + ky) & 255;
        }
        int h = hg*8 + r;
        g_yw[((b*CC + c)*HH + h)*M2 + ky] = make_float2(re, im);
    }
}

// ---------------- forward DFT along H: 256 -> 40 modes (+ 1/256 ortho scale) ----
__global__ void k_dfth(){
    __shared__ float2 sy[HH*M2];    // 40 KB
    __shared__ float  stc[256], sts[256];
    int tid = threadIdx.x;          // 800
    int c = blockIdx.x, b = blockIdx.y;
    if (tid < 256){ stc[tid] = g_tc[tid]; sts[tid] = g_ts[tid]; }
    const float2* yw = g_yw + (size_t)(b*CC + c)*HH*M2;
    for (int j = tid; j < HH*M2; j += 800) sy[j] = yw[j];
    __syncthreads();
    int kxi = tid / 20, ky = tid % 20;
    int kx  = (kxi < 20) ? kxi : (216 + kxi);   // negative freqs 236..255
    float re = 0.f, im = 0.f;
    int idx = 0;
    #pragma unroll 4
    for (int h = 0; h < HH; h++){
        float2 y = sy[h*M2 + ky];
        float cth = stc[idx], sth = sts[idx];
        re += y.x*cth + y.y*sth;     // y * e^{-i th}
        im += y.y*cth - y.x*sth;
        idx = (idx + kx) & 255;
    }
    const float sc = 1.0f/256.0f;    // rfft2 ortho norm
    g_xft[((b*CC + c)*40 + kxi)*M2 + ky] = make_float2(re*sc, im*sc);
}

// ---------------- per-mode complex channel mixing: out[b,o] = sum_i X[b,i]*W[i,o] ----
__global__ void k_mix(const float* __restrict__ w1, const float* __restrict__ w2, int layer){
    __shared__ float2 sx[BB*CC];     // X[b][i]
    int tid  = threadIdx.x;          // 512
    int mode = blockIdx.x;           // 800 modes
    int kxi = mode / 20, ky = mode % 20;
    int b = tid >> 6, i = tid & 63;
    sx[tid] = g_xft[((b*CC + i)*40 + kxi)*M2 + ky];
    __syncthreads();
    int o = i;
    const float* wbase; int kxl;
    const size_t lstride = (size_t)CC*CC*M1*M2*2;
    if (kxi < 20){ wbase = w1 + (size_t)layer*lstride; kxl = kxi; }
    else         { wbase = w2 + (size_t)layer*lstride; kxl = kxi - 20; }
    float re = 0.f, im = 0.f;
    const float* wp = wbase + ((size_t)o*(M1*M2) + kxl*M2 + ky)*2;
    #pragma unroll 8
    for (int ii = 0; ii < CC; ii++){
        float2 xv = sx[(b << 6) + ii];
        float wr = wp[0], wi = wp[1];
        re += xv.x*wr - xv.y*wi;
        im += xv.x*wi + xv.y*wr;
        wp += (size_t)CC*M1*M2*2;     // stride over i
    }
    g_oft[((b*CC + o)*40 + kxi)*M2 + ky] = make_float2(re, im);
}

// ---------------- inverse DFT along H (40 modes -> 256) ----------------
__global__ void k_idfth(){
    __shared__ float2 so[40*M2];     // 800 complex
    __shared__ float  stc[256], sts[256];
    int tid = threadIdx.x;           // 256
    int o = blockIdx.x, b = blockIdx.y;
    stc[tid] = g_tc[tid]; sts[tid] = g_ts[tid];
    const float2* op = g_oft + (size_t)(b*CC + o)*40*M2;
    for (int j = tid; j < 800; j += 256) so[j] = op[j];
    __syncthreads();
    int h = tid;
    float2* zout = g_zh + ((size_t)(b*CC + o)*HH + h)*M2;
    for (int ky = 0; ky < M2; ky++){
        float re = 0.f, im = 0.f;
        #pragma unroll
        for (int kxi = 0; kxi < 40; kxi++){
            int kx  = (kxi < 20) ? kxi : (216 + kxi);
            int idx = (h * kx) & 255;
            float2 ov = so[kxi*M2 + ky];
            float cth = stc[idx], sth = sts[idx];
            re += ov.x*cth - ov.y*sth;   // ov * e^{+i th}
            im += ov.x*sth + ov.y*cth;
        }
        zout[ky] = make_float2(re, im);
    }
}

// ---------------- merged 3x3 conv (includes 1x1 folded into center tap) ----------
__global__ void __launch_bounds__(256) k_conv(int insel, int outsel, int layer){
    __shared__ float sp[10][34];     // input patch (8+2)x(32+2), one ic at a time
    __shared__ float swt[32*9];      // 32 oc x 9 taps for current ic
    int tid = threadIdx.x;
    int tw0 = blockIdx.x * 32;
    int th0 = blockIdx.y * 8;
    int bz  = blockIdx.z;
    int b      = bz >> 1;
    int ocbase = (bz & 1) * 32;

    int ocq = tid >> 6;              // 0..3 -> 8 oc each
    int pg  = tid & 63;
    int pw  = pg & 31;
    int phq = pg >> 5;               // 0..1 -> 4 rows each
    const float* in = selbuf(insel) + ((size_t)(b*CC) << 16);

    float acc[8][4];
    #pragma unroll
    for (int u = 0; u < 8; u++)
        #pragma unroll
        for (int p = 0; p < 4; p++) acc[u][p] = 0.f;

    const float* wl = g_wm + layer*CC*CC*9;
    for (int ic = 0; ic < CC; ic++){
        const float* ip = in + ((size_t)ic << 16);
        for (int j = tid; j < 340; j += 256){
            int r = j / 34, cc2 = j % 34;
            int gh = th0 - 1 + r, gw = tw0 - 1 + cc2;
            float v = 0.f;
            if (gh >= 0 && gh < HH && gw >= 0 && gw < WW) v = ip[gh*WW + gw];
            sp[r][cc2] = v;
        }
        for (int j = tid; j < 288; j += 256){          // FIX: full 32x9 load with 256 threads
            int o = j / 9, t = j % 9;
            swt[j] = wl[((ocbase + o)*CC + ic)*9 + t];
        }
        __syncthreads();

        float rin[6][3];
        int rb = phq * 4;
        #pragma unroll
        for (int r = 0; r < 6; r++)
            #pragma unroll
            for (int cx = 0; cx < 3; cx++) rin[r][cx] = sp[rb + r][pw + cx];

        #pragma unroll
        for (int dy = 0; dy < 3; dy++)
            #pragma unroll
            for (int dx = 0; dx < 3; dx++)
                #pragma unroll
                for (int u = 0; u < 8; u++){
                    float wv = swt[(ocq*8 + u)*9 + dy*3 + dx];
                    #pragma unroll
                    for (int p = 0; p < 4; p++)
                        acc[u][p] += rin[p + dy][dx] * wv;
                }
        __syncthreads();
    }

    float* out = selbuf(outsel) + ((size_t)(b*CC) << 16);
    #pragma unroll
    for (int u = 0; u < 8; u++){
        int oc = ocbase + ocq*8 + u;
        float bv = g_bm[layer*CC + oc];
        #pragma unroll
        for (int p = 0; p < 4; p++){
            int gh = th0 + phq*4 + p;
            out[((size_t)oc << 16) + gh*WW + tw0 + pw] = acc[u][p] + bv;
        }
    }
}

// ---------------- inverse DFT along W (20 modes -> 256) + add + gelu -----------
__global__ void k_combine(int outsel, int dogelu){
    __shared__ float zr[20], zi[20];
    __shared__ float stc[256], sts[256];
    int tid = threadIdx.x;           // 256
    int row = blockIdx.x;            // (b*CC+o)*HH + h
    stc[tid] = g_tc[tid]; sts[tid] = g_ts[tid];
    if (tid < 20){
        float2 z = g_zh[(size_t)row*M2 + tid];
        zr[tid] = z.x; zi[tid] = z.y;
    }
    __syncthreads();
    int w = tid;
    float accv = zr[0];              // c2r convention: imag of DC ignored
    #pragma unroll
    for (int ky = 1; ky < 20; ky++){
        int idx = (w * ky) & 255;
        accv += 2.f * (zr[ky]*stc[idx] - zi[ky]*sts[idx]);
    }
    float x1 = accv * (1.0f/256.0f); // irfft2 ortho norm
    float* out = selbuf(outsel);
    size_t p = (size_t)row*256 + w;
    float v = out[p] + x1;
    if (dogelu) v = gelu_exact(v);
    out[p] = v;
}

// ---------------- head: fc1(64->128) + gelu + fc2(128->1) ----------------
__global__ void __launch_bounds__(128) k_fc(const float* __restrict__ w1,
        const float* __restrict__ b1, const float* __restrict__ w2,
        const float* __restrict__ b2, float* __restrict__ out, int sel){
    __shared__ float sw1[CC*128];    // 32 KB
    __shared__ float sin_[CC];
    __shared__ float spart[4];
    int tid = threadIdx.x;           // 128
    for (int j = tid; j < CC*128; j += 128) sw1[j] = w1[j];
    float myb1 = b1[tid];
    float myw2 = w2[tid];
    float b2v  = b2[0];
    const float* h = selbuf(sel);
    __syncthreads();
    int pbase = blockIdx.x * 64;
    for (int p = 0; p < 64; p++){
        int pix = pbase + p;
        int b = pix >> 16, hw = pix & 65535;
        if (tid < 64) sin_[tid] = h[((b*CC + tid) << 16) + hw];
        __syncthreads();
        float s = myb1;
        #pragma unroll 8
        for (int c2 = 0; c2 < CC; c2++) s += sin_[c2] * sw1[c2*128 + tid];
        float v = gelu_exact(s) * myw2;
        #pragma unroll
        for (int off = 16; off > 0; off >>= 1)
            v += __shfl_down_sync(0xffffffffu, v, off);
        if ((tid & 31) == 0) spart[tid >> 5] = v;
        __syncthreads();
        if (tid == 0) out[pix] = spart[0] + spart[1] + spart[2] + spart[3] + b2v;
        __syncthreads();
    }
}

// ---------------- launch ----------------
extern "C" void kernel_launch(void* const* d_in, const int* in_sizes, int n_in,
                              void* d_out, int out_size){
    const float* x     = (const float*)d_in[0];
    const float* fc0_w = (const float*)d_in[1];
    const float* fc0_b = (const float*)d_in[2];
    const float* w1    = (const float*)d_in[3];
    const float* w2    = (const float*)d_in[4];
    const float* chw   = (const float*)d_in[5];
    const float* chb   = (const float*)d_in[6];
    const float* cww   = (const float*)d_in[7];
    const float* cwb   = (const float*)d_in[8];
    const float* pww   = (const float*)d_in[9];
    const float* pwb   = (const float*)d_in[10];
    const float* fc1_w = (const float*)d_in[11];
    const float* fc1_b = (const float*)d_in[12];
    const float* fc2_w = (const float*)d_in[13];
    const float* fc2_b = (const float*)d_in[14];
    float* out = (float*)d_out;

    k_init_tw<<<1, 256>>>();
    k_merge<<<(NL*CC*CC*9 + 255)/256, 256>>>(chw, cww, pww, chb, cwb, pwb);
    k_fc0<<<NPIX/256, 256>>>(x, fc0_w, fc0_b);

    int cur = 0;
    for (int l = 0; l < NL; l++){
        int nxt = cur ^ 1;
        k_dftw   <<<dim3(32, CC, BB), 256>>>(cur);
        k_dfth   <<<dim3(CC, BB),     800>>>();
        k_mix    <<<800,              512>>>(w1, w2, l);
        k_idfth  <<<dim3(CC, BB),     256>>>();
        k_conv   <<<dim3(8, 32, BB*2),256>>>(cur, nxt, l);
        k_combine<<<BB*CC*HH,         256>>>(nxt, (l < NL-1) ? 1 : 0);
        cur = nxt;
    }
    k_fc<<<NPIX/64, 128>>>(fc1_w, fc1_b, fc2_w, fc2_b, out, cur);
}

// round 3
// speedup vs baseline: 1.4872x; 1.4872x over previous
#include <cuda_runtime.h>
#include <math.h>

#define BB 8
#define CC 64
#define HH 256
#define WW 256
#define M1 20
#define M2 20
#define NL 4
#define HW 65536
#define NPIX (BB*HH*WW)   // 524288

// ---------------- static device scratch ----------------
__device__ float  g_bufA[BB*CC*HW];
__device__ float  g_bufB[BB*CC*HW];
__device__ float2 g_yw [BB*CC*HH*M2];
__device__ float2 g_xft[BB*CC*2*M1*M2];
__device__ float2 g_oft[BB*CC*2*M1*M2];
__device__ float2 g_zh [BB*CC*HH*M2];
__device__ float  g_wt [NL*CC*9*CC];         // merged weights, layout [l][ic][tap][oc]
__device__ float  g_bm [NL*CC];
__device__ float  g_tc [256];
__device__ float  g_ts [256];
__device__ float2 g_tcs[256];                // (cos, sin) interleaved

__device__ __forceinline__ float* selbuf(int s){ return s ? g_bufB : g_bufA; }

__device__ __forceinline__ float gelu_exact(float x){
    return 0.5f * x * (1.0f + erff(x * 0.7071067811865476f));
}

// ---------------- twiddle init ----------------
__global__ void k_init_tw(){
    int i = threadIdx.x;
    double th = 6.283185307179586476925286766559 * (double)i / 256.0;
    float c = (float)cos(th), s = (float)sin(th);
    g_tc[i] = c; g_ts[i] = s;
    g_tcs[i] = make_float2(c, s);
}

// ---------------- merge convh+convw+pw, transpose to [l][ic][tap][oc] ----------
__global__ void k_merge(const float* __restrict__ ch, const float* __restrict__ cw,
                        const float* __restrict__ pw, const float* __restrict__ bh,
                        const float* __restrict__ bw, const float* __restrict__ bp){
    int idx = blockIdx.x * 256 + threadIdx.x;
    const int total = NL*CC*9*CC;
    if (idx < total){
        int oc  = idx & 63;
        int tap = (idx >> 6) % 9;
        int ic  = (idx / (9*64)) & 63;
        int l   = idx / (64*9*64);
        int src = ((l*CC + oc)*CC + ic)*9 + tap;
        float v = ch[src] + cw[src];
        if (tap == 4) v += pw[(l*CC + oc)*CC + ic];
        g_wt[idx] = v;
    }
    if (idx < NL*CC) g_bm[idx] = bh[idx] + bw[idx] + bp[idx];
}

// ---------------- fc0 lift: (B,H,W,3) -> (B,C,H,W) ----------------
__global__ void k_fc0(const float* __restrict__ x, const float* __restrict__ w,
                      const float* __restrict__ bias){
    __shared__ float sw[3*CC];
    __shared__ float sb[CC];
    int tid = threadIdx.x;
    if (tid < 3*CC) sw[tid] = w[tid];
    if (tid < CC)   sb[tid] = bias[tid];
    __syncthreads();
    int pix = blockIdx.x * 256 + tid;
    int b  = pix >> 16;
    int hw = pix & 65535;
    float x0 = x[pix*3+0], x1 = x[pix*3+1], x2 = x[pix*3+2];
    float* out = selbuf(0);
    #pragma unroll 8
    for (int c = 0; c < CC; c++){
        float v = x0*sw[c] + x1*sw[64+c] + x2*sw[128+c] + sb[c];
        out[((b*CC + c) << 16) + hw] = v;
    }
}

// ---------------- forward DFT along W: 256 -> 20 modes (4 rows/thread) ---------
__global__ void __launch_bounds__(256) k_dftw(int insel){
    __shared__ float  srow[32][257];     // padded: no bank conflict across rows
    __shared__ float2 stcs[256];
    int tid = threadIdx.x;     // 256
    int hg  = blockIdx.x;      // 0..7 (32 rows each)
    int c   = blockIdx.y;
    int b   = blockIdx.z;
    stcs[tid] = g_tcs[tid];
    const float* in = selbuf(insel) + ((b*CC + c) << 16) + hg*32*WW;
    for (int j = tid; j < 32*256; j += 256) srow[j >> 8][j & 255] = in[j];
    __syncthreads();
    if (tid < 160){
        int rg = tid / 20, ky = tid % 20;
        const float* r0 = srow[rg*4+0];
        const float* r1 = srow[rg*4+1];
        const float* r2 = srow[rg*4+2];
        const float* r3 = srow[rg*4+3];
        float re0=0.f,re1=0.f,re2=0.f,re3=0.f;
        float im0=0.f,im1=0.f,im2=0.f,im3=0.f;
        int idx = 0;
        #pragma unroll 4
        for (int w = 0; w < WW; w++){
            float2 t = stcs[idx];
            float v0=r0[w], v1=r1[w], v2=r2[w], v3=r3[w];
            re0 += v0*t.x; im0 -= v0*t.y;
            re1 += v1*t.x; im1 -= v1*t.y;
            re2 += v2*t.x; im2 -= v2*t.y;
            re3 += v3*t.x; im3 -= v3*t.y;
            idx = (idx + ky) & 255;
        }
        int hbase = hg*32 + rg*4;
        float2* yw = g_yw + (size_t)(b*CC + c)*HH*M2;
        yw[(hbase+0)*M2 + ky] = make_float2(re0, im0);
        yw[(hbase+1)*M2 + ky] = make_float2(re1, im1);
        yw[(hbase+2)*M2 + ky] = make_float2(re2, im2);
        yw[(hbase+3)*M2 + ky] = make_float2(re3, im3);
    }
}

// ---------------- forward DFT along H: 256 -> 40 modes -------------------------
__global__ void k_dfth(){
    __shared__ float2 sy[HH*M2];
    __shared__ float  stc[256], sts[256];
    int tid = threadIdx.x;          // 800
    int c = blockIdx.x, b = blockIdx.y;
    if (tid < 256){ stc[tid] = g_tc[tid]; sts[tid] = g_ts[tid]; }
    const float2* yw = g_yw + (size_t)(b*CC + c)*HH*M2;
    for (int j = tid; j < HH*M2; j += 800) sy[j] = yw[j];
    __syncthreads();
    int kxi = tid / 20, ky = tid % 20;
    int kx  = (kxi < 20) ? kxi : (216 + kxi);
    float re = 0.f, im = 0.f;
    int idx = 0;
    #pragma unroll 4
    for (int h = 0; h < HH; h++){
        float2 y = sy[h*M2 + ky];
        float cth = stc[idx], sth = sts[idx];
        re += y.x*cth + y.y*sth;
        im += y.y*cth - y.x*sth;
        idx = (idx + kx) & 255;
    }
    const float sc = 1.0f/256.0f;
    g_xft[((b*CC + c)*40 + kxi)*M2 + ky] = make_float2(re*sc, im*sc);
}

// ---------------- per-mode complex channel mixing ------------------------------
__global__ void k_mix(const float* __restrict__ w1, const float* __restrict__ w2, int layer){
    __shared__ float2 sx[BB*CC];
    int tid  = threadIdx.x;          // 512
    int mode = blockIdx.x;           // 800
    int kxi = mode / 20, ky = mode % 20;
    int b = tid >> 6, i = tid & 63;
    sx[tid] = g_xft[((b*CC + i)*40 + kxi)*M2 + ky];
    __syncthreads();
    int o = i;
    const float* wbase; int kxl;
    const size_t lstride = (size_t)CC*CC*M1*M2*2;
    if (kxi < 20){ wbase = w1 + (size_t)layer*lstride; kxl = kxi; }
    else         { wbase = w2 + (size_t)layer*lstride; kxl = kxi - 20; }
    float re = 0.f, im = 0.f;
    const float* wp = wbase + ((size_t)o*(M1*M2) + kxl*M2 + ky)*2;
    #pragma unroll 8
    for (int ii = 0; ii < CC; ii++){
        float2 xv = sx[(b << 6) + ii];
        float wr = wp[0], wi = wp[1];
        re += xv.x*wr - xv.y*wi;
        im += xv.x*wi + xv.y*wr;
        wp += (size_t)CC*M1*M2*2;
    }
    g_oft[((b*CC + o)*40 + kxi)*M2 + ky] = make_float2(re, im);
}

// ---------------- inverse DFT along H (40 modes -> 256) ------------------------
__global__ void k_idfth(){
    __shared__ float2 so[40*M2];
    __shared__ float  stc[256], sts[256];
    int tid = threadIdx.x;           // 256
    int o = blockIdx.x, b = blockIdx.y;
    stc[tid] = g_tc[tid]; sts[tid] = g_ts[tid];
    const float2* op = g_oft + (size_t)(b*CC + o)*40*M2;
    for (int j = tid; j < 800; j += 256) so[j] = op[j];
    __syncthreads();
    int h = tid;
    float2* zout = g_zh + ((size_t)(b*CC + o)*HH + h)*M2;
    for (int ky = 0; ky < M2; ky++){
        float re = 0.f, im = 0.f;
        #pragma unroll
        for (int kxi = 0; kxi < 40; kxi++){
            int kx  = (kxi < 20) ? kxi : (216 + kxi);
            int idx = (h * kx) & 255;
            float2 ov = so[kxi*M2 + ky];
            float cth = stc[idx], sth = sts[idx];
            re += ov.x*cth - ov.y*sth;
            im += ov.x*sth + ov.y*cth;
        }
        zout[ky] = make_float2(re, im);
    }
}

// ---- merged 3x3 conv (FFMA2 dual-fp32) + fused inverse-W DFT + add + gelu -----
__global__ void __launch_bounds__(256) k_conv(int insel, int outsel, int layer, int dogelu){
    __shared__ float  sp[10][34];
    __shared__ float  swt[9][32];      // [tap][oc_local]
    __shared__ float2 sz[32*8*20];     // 40KB: [ocl][hl][ky] spectral rows for epilogue
    int tid = threadIdx.x;
    int tw0 = blockIdx.x * 32;
    int th0 = blockIdx.y * 8;
    int bz  = blockIdx.z;
    int b      = bz >> 1;
    int ocbase = (bz & 1) * 32;

    int ocq = tid >> 6;              // 0..3 -> 8 oc each (4 float2 pairs)
    int pg  = tid & 63;
    int pw  = pg & 31;
    int phq = pg >> 5;               // 0..1 -> 4 rows each
    const float* in = selbuf(insel) + ((size_t)(b*CC) << 16);

    unsigned long long acc2[4][4];   // [oc pair][px] packed f32x2
    #pragma unroll
    for (int u = 0; u < 4; u++)
        #pragma unroll
        for (int p = 0; p < 4; p++) acc2[u][p] = 0ULL;

    const float* wt = g_wt + (size_t)layer*CC*9*CC;
    for (int ic = 0; ic < CC; ic++){
        const float* ip = in + ((size_t)ic << 16);
        for (int j = tid; j < 340; j += 256){
            int r = j / 34, c2 = j % 34;
            int gh = th0 - 1 + r, gw = tw0 - 1 + c2;
            float v = 0.f;
            if (gh >= 0 && gh < HH && gw >= 0 && gw < WW) v = ip[gh*WW + gw];
            sp[r][c2] = v;
        }
        for (int j = tid; j < 288; j += 256){
            int tap = j >> 5, ocl = j & 31;
            swt[tap][ocl] = wt[((size_t)ic*9 + tap)*CC + ocbase + ocl];
        }
        __syncthreads();

        float rin[6][3];
        int rb = phq * 4;
        #pragma unroll
        for (int r = 0; r < 6; r++)
            #pragma unroll
            for (int cx = 0; cx < 3; cx++) rin[r][cx] = sp[rb + r][pw + cx];

        #pragma unroll
        for (int dy = 0; dy < 3; dy++){
            #pragma unroll
            for (int dx = 0; dx < 3; dx++){
                int tap = dy*3 + dx;
                unsigned long long wp4[4];
                #pragma unroll
                for (int u = 0; u < 4; u++){
                    float2 wv = *(const float2*)&swt[tap][ocq*8 + u*2];
                    asm("mov.b64 %0, {%1,%2};" : "=l"(wp4[u]) : "f"(wv.x), "f"(wv.y));
                }
                #pragma unroll
                for (int p = 0; p < 4; p++){
                    float rr = rin[p + dy][dx];
                    unsigned long long rp;
                    asm("mov.b64 %0, {%1,%1};" : "=l"(rp) : "f"(rr));
                    #pragma unroll
                    for (int u = 0; u < 4; u++)
                        asm("fma.rn.f32x2 %0, %1, %2, %0;" : "+l"(acc2[u][p]) : "l"(rp), "l"(wp4[u]));
                }
            }
        }
        __syncthreads();
    }

    // stage spectral rows for fused irfft-W: 32 oc x 8 h x 20 ky
    for (int j = tid; j < 32*8*20; j += 256){
        int ocl = j / 160, rem = j % 160, hl = rem / 20, ky = rem % 20;
        sz[j] = g_zh[((size_t)(b*CC + ocbase + ocl)*HH + th0 + hl)*M2 + ky];
    }
    __syncthreads();

    int w = tw0 + pw;
    float c1 = g_tc[w], s1 = g_ts[w];
    float* out = selbuf(outsel) + ((size_t)(b*CC) << 16);
    #pragma unroll
    for (int p = 0; p < 4; p++){
        int hl = phq*4 + p;
        int gh = th0 + hl;
        float accv[8];
        #pragma unroll
        for (int u = 0; u < 8; u++) accv[u] = sz[((ocq*8 + u)*8 + hl)*20].x;
        float cr = c1, ci = s1;
        for (int ky = 1; ky < 20; ky++){
            #pragma unroll
            for (int u = 0; u < 8; u++){
                float2 z = sz[((ocq*8 + u)*8 + hl)*20 + ky];
                accv[u] += 2.f*(z.x*cr - z.y*ci);
            }
            float nr = cr*c1 - ci*s1;
            ci = cr*s1 + ci*c1;
            cr = nr;
        }
        #pragma unroll
        for (int u = 0; u < 4; u++){
            float lo, hi;
            asm("mov.b64 {%0,%1}, %2;" : "=f"(lo), "=f"(hi) : "l"(acc2[u][p]));
            int oc0 = ocbase + ocq*8 + u*2;
            float v0 = lo + g_bm[layer*CC + oc0]     + accv[u*2]   * (1.0f/256.0f);
            float v1 = hi + g_bm[layer*CC + oc0 + 1] + accv[u*2+1] * (1.0f/256.0f);
            if (dogelu){ v0 = gelu_exact(v0); v1 = gelu_exact(v1); }
            out[((size_t)oc0     << 16) + gh*WW + w] = v0;
            out[((size_t)(oc0+1) << 16) + gh*WW + w] = v1;
        }
    }
}

// ---------------- head: fc1(64->128) + gelu + fc2(128->1) ----------------
__global__ void __launch_bounds__(128) k_fc(const float* __restrict__ w1,
        const float* __restrict__ b1, const float* __restrict__ w2,
        const float* __restrict__ b2, float* __restrict__ out, int sel){
    __shared__ float sw1[CC*128];
    __shared__ float sin_[CC];
    __shared__ float spart[4];
    int tid = threadIdx.x;           // 128
    for (int j = tid; j < CC*128; j += 128) sw1[j] = w1[j];
    float myb1 = b1[tid];
    float myw2 = w2[tid];
    float b2v  = b2[0];
    const float* h = selbuf(sel);
    __syncthreads();
    int pbase = blockIdx.x * 32;
    for (int p = 0; p < 32; p++){
        int pix = pbase + p;
        int b = pix >> 16, hw = pix & 65535;
        if (tid < 64) sin_[tid] = h[((b*CC + tid) << 16) + hw];
        __syncthreads();
        float s = myb1;
        #pragma unroll 8
        for (int c2 = 0; c2 < CC; c2++) s += sin_[c2] * sw1[c2*128 + tid];
        float v = gelu_exact(s) * myw2;
        #pragma unroll
        for (int off = 16; off > 0; off >>= 1)
            v += __shfl_down_sync(0xffffffffu, v, off);
        if ((tid & 31) == 0) spart[tid >> 5] = v;
        __syncthreads();
        if (tid == 0) out[pix] = spart[0] + spart[1] + spart[2] + spart[3] + b2v;
        __syncthreads();
    }
}

// ---------------- launch ----------------
extern "C" void kernel_launch(void* const* d_in, const int* in_sizes, int n_in,
                              void* d_out, int out_size){
    const float* x     = (const float*)d_in[0];
    const float* fc0_w = (const float*)d_in[1];
    const float* fc0_b = (const float*)d_in[2];
    const float* w1    = (const float*)d_in[3];
    const float* w2    = (const float*)d_in[4];
    const float* chw   = (const float*)d_in[5];
    const float* chb   = (const float*)d_in[6];
    const float* cww   = (const float*)d_in[7];
    const float* cwb   = (const float*)d_in[8];
    const float* pww   = (const float*)d_in[9];
    const float* pwb   = (const float*)d_in[10];
    const float* fc1_w = (const float*)d_in[11];
    const float* fc1_b = (const float*)d_in[12];
    const float* fc2_w = (const float*)d_in[13];
    const float* fc2_b = (const float*)d_in[14];
    float* out = (float*)d_out;

    k_init_tw<<<1, 256>>>();
    k_merge<<<(NL*CC*9*CC + 255)/256, 256>>>(chw, cww, pww, chb, cwb, pwb);
    k_fc0<<<NPIX/256, 256>>>(x, fc0_w, fc0_b);

    int cur = 0;
    for (int l = 0; l < NL; l++){
        int nxt = cur ^ 1;
        k_dftw <<<dim3(8, CC, BB),  256>>>(cur);
        k_dfth <<<dim3(CC, BB),     800>>>();
        k_mix  <<<800,              512>>>(w1, w2, l);
        k_idfth<<<dim3(CC, BB),     256>>>();
        k_conv <<<dim3(8, 32, BB*2),256>>>(cur, nxt, l, (l < NL-1) ? 1 : 0);
        cur = nxt;
    }
    k_fc<<<NPIX/32, 128>>>(fc1_w, fc1_b, fc2_w, fc2_b, out, cur);
}

// round 5
// speedup vs baseline: 1.7624x; 1.1850x over previous
#include <cuda_runtime.h>
#include <cuda_bf16.h>
#include <math.h>
#include <stdint.h>

#define BB 8
#define CC 64
#define HH 256
#define WW 256
#define M1 20
#define M2 20
#define NL 4
#define HW 65536
#define NPIX (BB*HH*WW)

// ---------------- static device scratch ----------------
__device__ float  g_bufA[BB*CC*HW];
__device__ float  g_bufB[BB*CC*HW];
__device__ float2 g_yw [BB*CC*HH*M2];
__device__ float2 g_xft[BB*CC*2*M1*M2];
__device__ float2 g_oft[BB*CC*2*M1*M2];
__device__ float2 g_zh [BB*CC*HH*M2];
__device__ float  g_bm [NL*CC];
__device__ float  g_tc [256];
__device__ float  g_ts [256];
__device__ float2 g_tcs[256];
// bf16 hi/lo split weights: [l][dy][s*3+dx][n*64+ic]
__device__ __nv_bfloat16 g_wbf2[NL][3][6][64*64];

__device__ __forceinline__ float* selbuf(int s){ return s ? g_bufB : g_bufA; }
__device__ __forceinline__ float gelu_exact(float x){
    return 0.5f * x * (1.0f + erff(x * 0.7071067811865476f));
}

// ---- smem layout for k_conv_mma (dynamic) ----
#define ICP 72                           // padded ic stride (36 banks -> conflict-free frags)
#define AH_OFF 0                         // bf16 [3][130][ICP]  = 56160 B
#define AL_OFF 56160
#define WB_OFF 112320                    // bf16 [6][64][ICP]   = 55296 B (per-dy staging)
#define SZ_OFF 167616                    // float2 [64][20]     = 10240 B
#define SMEM_CONV 177856

__device__ __forceinline__ void mma_bf16(float* c, const uint32_t* a, uint32_t b0, uint32_t b1){
    asm volatile("mma.sync.aligned.m16n8k16.row.col.f32.bf16.bf16.f32 "
        "{%0,%1,%2,%3}, {%4,%5,%6,%7}, {%8,%9}, {%0,%1,%2,%3};"
        : "+f"(c[0]), "+f"(c[1]), "+f"(c[2]), "+f"(c[3])
        : "r"(a[0]), "r"(a[1]), "r"(a[2]), "r"(a[3]), "r"(b0), "r"(b1));
}

// ---------------- twiddle init ----------------
__global__ void k_init_tw(){
    int i = threadIdx.x;
    double th = 6.283185307179586476925286766559 * (double)i / 256.0;
    float c = (float)cos(th), s = (float)sin(th);
    g_tc[i] = c; g_ts[i] = s;
    g_tcs[i] = make_float2(c, s);
}

// ------- merge convh+convw+pw -> bf16 hi/lo split, [l][dy][s*3+dx][n][ic] -------
__global__ void k_merge(const float* __restrict__ ch, const float* __restrict__ cw,
                        const float* __restrict__ pw, const float* __restrict__ bh,
                        const float* __restrict__ bw, const float* __restrict__ bp){
    int idx = blockIdx.x * 256 + threadIdx.x;
    const int total = NL*9*64*64;
    if (idx < total){
        int ic = idx & 63;
        int n  = (idx >> 6) & 63;
        int t  = (idx >> 12) % 9;        // dy*3+dx
        int l  = idx / (9*64*64);
        int dy = t / 3, dx = t % 3;
        int src = ((l*CC + n)*CC + ic)*9 + t;
        float v = ch[src] + cw[src];
        if (t == 4) v += pw[(l*CC + n)*CC + ic];
        __nv_bfloat16 hb = __float2bfloat16(v);
        float hf = __bfloat162float(hb);
        __nv_bfloat16 lb = __float2bfloat16(v - hf);
        g_wbf2[l][dy][0*3+dx][n*64+ic] = hb;
        g_wbf2[l][dy][1*3+dx][n*64+ic] = lb;
    }
    if (idx < NL*CC) g_bm[idx] = bh[idx] + bw[idx] + bp[idx];
}

// ---------------- fc0 lift ----------------
__global__ void k_fc0(const float* __restrict__ x, const float* __restrict__ w,
                      const float* __restrict__ bias){
    __shared__ float sw[3*CC];
    __shared__ float sb[CC];
    int tid = threadIdx.x;
    if (tid < 3*CC) sw[tid] = w[tid];
    if (tid < CC)   sb[tid] = bias[tid];
    __syncthreads();
    int pix = blockIdx.x * 256 + tid;
    int b  = pix >> 16;
    int hw = pix & 65535;
    float x0 = x[pix*3+0], x1 = x[pix*3+1], x2 = x[pix*3+2];
    float* out = selbuf(0);
    #pragma unroll 8
    for (int c = 0; c < CC; c++){
        float v = x0*sw[c] + x1*sw[64+c] + x2*sw[128+c] + sb[c];
        out[((b*CC + c) << 16) + hw] = v;
    }
}

// ---------------- forward DFT along W: 256 -> 20 modes ----------------
__global__ void __launch_bounds__(256) k_dftw(int insel){
    __shared__ float  srow[32][257];
    __shared__ float2 stcs[256];
    int tid = threadIdx.x;
    int hg  = blockIdx.x;
    int c   = blockIdx.y;
    int b   = blockIdx.z;
    stcs[tid] = g_tcs[tid];
    const float* in = selbuf(insel) + ((b*CC + c) << 16) + hg*32*WW;
    for (int j = tid; j < 32*256; j += 256) srow[j >> 8][j & 255] = in[j];
    __syncthreads();
    if (tid < 160){
        int rg = tid / 20, ky = tid % 20;
        const float* r0 = srow[rg*4+0];
        const float* r1 = srow[rg*4+1];
        const float* r2 = srow[rg*4+2];
        const float* r3 = srow[rg*4+3];
        float re0=0.f,re1=0.f,re2=0.f,re3=0.f;
        float im0=0.f,im1=0.f,im2=0.f,im3=0.f;
        int idx = 0;
        #pragma unroll 4
        for (int w = 0; w < WW; w++){
            float2 t = stcs[idx];
            float v0=r0[w], v1=r1[w], v2=r2[w], v3=r3[w];
            re0 += v0*t.x; im0 -= v0*t.y;
            re1 += v1*t.x; im1 -= v1*t.y;
            re2 += v2*t.x; im2 -= v2*t.y;
            re3 += v3*t.x; im3 -= v3*t.y;
            idx = (idx + ky) & 255;
        }
        int hbase = hg*32 + rg*4;
        float2* yw = g_yw + (size_t)(b*CC + c)*HH*M2;
        yw[(hbase+0)*M2 + ky] = make_float2(re0, im0);
        yw[(hbase+1)*M2 + ky] = make_float2(re1, im1);
        yw[(hbase+2)*M2 + ky] = make_float2(re2, im2);
        yw[(hbase+3)*M2 + ky] = make_float2(re3, im3);
    }
}

// ---------------- forward DFT along H: 256 -> 40 modes ----------------
__global__ void k_dfth(){
    __shared__ float2 sy[HH*M2];
    __shared__ float  stc[256], sts[256];
    int tid = threadIdx.x;          // 800
    int c = blockIdx.x, b = blockIdx.y;
    if (tid < 256){ stc[tid] = g_tc[tid]; sts[tid] = g_ts[tid]; }
    const float2* yw = g_yw + (size_t)(b*CC + c)*HH*M2;
    for (int j = tid; j < HH*M2; j += 800) sy[j] = yw[j];
    __syncthreads();
    int kxi = tid / 20, ky = tid % 20;
    int kx  = (kxi < 20) ? kxi : (216 + kxi);
    float re = 0.f, im = 0.f;
    int idx = 0;
    #pragma unroll 4
    for (int h = 0; h < HH; h++){
        float2 y = sy[h*M2 + ky];
        float cth = stc[idx], sth = sts[idx];
        re += y.x*cth + y.y*sth;
        im += y.y*cth - y.x*sth;
        idx = (idx + kx) & 255;
    }
    const float sc = 1.0f/256.0f;
    g_xft[((b*CC + c)*40 + kxi)*M2 + ky] = make_float2(re*sc, im*sc);
}

// ---------------- per-mode complex channel mixing ------------------------------
__global__ void k_mix(const float* __restrict__ w1, const float* __restrict__ w2, int layer){
    __shared__ float2 sx[BB*CC];
    int tid  = threadIdx.x;          // 512
    int mode = blockIdx.x;           // 800
    int kxi = mode / 20, ky = mode % 20;
    int b = tid >> 6, i = tid & 63;
    sx[tid] = g_xft[((b*CC + i)*40 + kxi)*M2 + ky];
    __syncthreads();
    int o = i;
    const float* wbase; int kxl;
    const size_t lstride = (size_t)CC*CC*M1*M2*2;
    if (kxi < 20){ wbase = w1 + (size_t)layer*lstride; kxl = kxi; }
    else         { wbase = w2 + (size_t)layer*lstride; kxl = kxi - 20; }
    float re = 0.f, im = 0.f;
    const float* wp = wbase + ((size_t)o*(M1*M2) + kxl*M2 + ky)*2;
    #pragma unroll 8
    for (int ii = 0; ii < CC; ii++){
        float2 xv = sx[(b << 6) + ii];
        float wr = wp[0], wi = wp[1];
        re += xv.x*wr - xv.y*wi;
        im += xv.x*wi + xv.y*wr;
        wp += (size_t)CC*M1*M2*2;
    }
    g_oft[((b*CC + o)*40 + kxi)*M2 + ky] = make_float2(re, im);
}

// ---------------- inverse DFT along H (40 modes -> 256) ------------------------
__global__ void k_idfth(){
    __shared__ float2 so[40*M2];
    __shared__ float  stc[256], sts[256];
    int tid = threadIdx.x;           // 256
    int o = blockIdx.x, b = blockIdx.y;
    stc[tid] = g_tc[tid]; sts[tid] = g_ts[tid];
    const float2* op = g_oft + (size_t)(b*CC + o)*40*M2;
    for (int j = tid; j < 800; j += 256) so[j] = op[j];
    __syncthreads();
    int h = tid;
    float2* zout = g_zh + ((size_t)(b*CC + o)*HH + h)*M2;
    for (int ky = 0; ky < M2; ky++){
        float re = 0.f, im = 0.f;
        #pragma unroll
        for (int kxi = 0; kxi < 40; kxi++){
            int kx  = (kxi < 20) ? kxi : (216 + kxi);
            int idx = (h * kx) & 255;
            float2 ov = so[kxi*M2 + ky];
            float cth = stc[idx], sth = sts[idx];
            re += ov.x*cth - ov.y*sth;
            im += ov.x*sth + ov.y*cth;
        }
        zout[ky] = make_float2(re, im);
    }
}

// ======== mma.sync bf16 implicit-GEMM 3x3 conv + fused irfft-W + bias + gelu ===
// Block 512 thr: tile M=128 px x N=64 oc. K = 3dy x 3dx x 64ic, bf16 hi/lo 3-GEMM.
__global__ void __launch_bounds__(512) k_conv_mma(int insel, int outsel, int layer, int dogelu){
    extern __shared__ unsigned char smem[];
    __nv_bfloat16* sAh = (__nv_bfloat16*)(smem + AH_OFF);
    __nv_bfloat16* sAl = (__nv_bfloat16*)(smem + AL_OFF);
    __nv_bfloat16* sB  = (__nv_bfloat16*)(smem + WB_OFF);
    float2*        sz  = (float2*)      (smem + SZ_OFF);

    int tid = threadIdx.x, wid = tid >> 5, lane = tid & 31;
    int w0 = blockIdx.x * 128;
    int h  = blockIdx.y;
    int b  = blockIdx.z;
    const float* in = selbuf(insel) + ((size_t)(b*CC) << 16);

    // ---- stage A (3 dy rows, hi/lo split) + spectral rows ----
    #pragma unroll
    for (int dy = 0; dy < 3; dy++){
        int gh = h + dy - 1;
        if (gh < 0 || gh >= HH) continue;
        const float* rp = in + gh*WW;
        for (int idx = tid; idx < 130*64; idx += 512){
            int ic = idx / 130, w = idx % 130;
            int gw = w0 - 1 + w;
            float v = 0.f;
            if (gw >= 0 && gw < WW) v = rp[((size_t)ic << 16) + gw];
            __nv_bfloat16 hb = __float2bfloat16(v);
            __nv_bfloat16 lb = __float2bfloat16(v - __bfloat162float(hb));
            int o = (dy*130 + w)*ICP + ic;
            sAh[o] = hb; sAl[o] = lb;
        }
    }
    for (int idx = tid; idx < 64*20; idx += 512){
        int oc = idx / 20, ky = idx % 20;
        sz[idx] = g_zh[((size_t)(b*CC + oc)*HH + h)*M2 + ky];
    }

    int mwarp = (wid & 7) * 16;       // px base of this warp
    int nhalf = (wid >> 3) * 32;      // oc base of this warp
    int grp   = lane >> 2;            // 0..7
    int t2    = (lane & 3) * 2;

    float c[4][4];
    #pragma unroll
    for (int nb = 0; nb < 4; nb++)
        #pragma unroll
        for (int j = 0; j < 4; j++) c[nb][j] = 0.f;

    int row0 = mwarp + grp;           // A rows (px)
    for (int dy = 0; dy < 3; dy++){
        int gh = h + dy - 1;
        if (gh < 0 || gh >= HH) continue;
        __syncthreads();              // prior consumers done before sB overwrite
        {
            const __nv_bfloat16* wsrc = &g_wbf2[layer][dy][0][0];
            for (int idx = tid; idx < 6*64*64; idx += 512){
                int ic = idx & 63, n = (idx >> 6) & 63, r = idx >> 12;
                sB[(r*64 + n)*ICP + ic] = wsrc[idx];
            }
        }
        __syncthreads();

        #pragma unroll
        for (int dx = 0; dx < 3; dx++){
            const __nv_bfloat16* a0h = sAh + (dy*130 + row0 + dx)*ICP;
            const __nv_bfloat16* a1h = a0h + 8*ICP;
            const __nv_bfloat16* a0l = sAl + (dy*130 + row0 + dx)*ICP;
            const __nv_bfloat16* a1l = a0l + 8*ICP;
            #pragma unroll
            for (int kk = 0; kk < 4; kk++){
                int kc = kk*16 + t2;
                uint32_t ah[4], al[4];
                ah[0] = *(const uint32_t*)(a0h + kc);
                ah[1] = *(const uint32_t*)(a1h + kc);
                ah[2] = *(const uint32_t*)(a0h + kc + 8);
                ah[3] = *(const uint32_t*)(a1h + kc + 8);
                al[0] = *(const uint32_t*)(a0l + kc);
                al[1] = *(const uint32_t*)(a1l + kc);
                al[2] = *(const uint32_t*)(a0l + kc + 8);
                al[3] = *(const uint32_t*)(a1l + kc + 8);
                #pragma unroll
                for (int nb = 0; nb < 4; nb++){
                    int n = nhalf + nb*8 + grp;
                    const __nv_bfloat16* bh = sB + ((0*3+dx)*64 + n)*ICP + kc;
                    const __nv_bfloat16* bl = sB + ((1*3+dx)*64 + n)*ICP + kc;
                    uint32_t bh0 = *(const uint32_t*)(bh);
                    uint32_t bh1 = *(const uint32_t*)(bh + 8);
                    uint32_t bl0 = *(const uint32_t*)(bl);
                    uint32_t bl1 = *(const uint32_t*)(bl + 8);
                    mma_bf16(c[nb], ah, bh0, bh1);   // hi*hi
                    mma_bf16(c[nb], ah, bl0, bl1);   // hi*lo
                    mma_bf16(c[nb], al, bh0, bh1);   // lo*hi
                }
            }
        }
        __syncthreads();
    }
    __syncthreads();   // ensure sz visible even if all dy skipped staging path order

    // ---- fused irfft-W + bias + gelu epilogue ----
    float bias[8];
    #pragma unroll
    for (int nb = 0; nb < 4; nb++){
        int oc = nhalf + nb*8 + t2;
        bias[nb*2+0] = g_bm[layer*CC + oc];
        bias[nb*2+1] = g_bm[layer*CC + oc + 1];
    }
    float* out = selbuf(outsel) + ((size_t)(b*CC) << 16);
    #pragma unroll
    for (int half = 0; half < 2; half++){
        int m  = mwarp + grp + half*8;
        int wc = w0 + m;
        float c1 = g_tc[wc], s1 = g_ts[wc];
        float acc[8];
        #pragma unroll
        for (int nb = 0; nb < 4; nb++){
            int oc = nhalf + nb*8 + t2;
            acc[nb*2+0] = sz[oc*20].x;
            acc[nb*2+1] = sz[(oc+1)*20].x;
        }
        float cr = c1, ci = s1;
        for (int ky = 1; ky < 20; ky++){
            #pragma unroll
            for (int nb = 0; nb < 4; nb++){
                int oc = nhalf + nb*8 + t2;
                float2 z0 = sz[oc*20 + ky];
                float2 z1 = sz[(oc+1)*20 + ky];
                acc[nb*2+0] += 2.f*(z0.x*cr - z0.y*ci);
                acc[nb*2+1] += 2.f*(z1.x*cr - z1.y*ci);
            }
            float nr = cr*c1 - ci*s1;
            ci = cr*s1 + ci*c1;
            cr = nr;
        }
        #pragma unroll
        for (int nb = 0; nb < 4; nb++){
            int oc = nhalf + nb*8 + t2;
            #pragma unroll
            for (int j = 0; j < 2; j++){
                float v = c[nb][half*2 + j] + bias[nb*2+j] + acc[nb*2+j]*(1.0f/256.0f);
                if (dogelu) v = gelu_exact(v);
                out[((size_t)(oc+j) << 16) + h*WW + wc] = v;
            }
        }
    }
}

// ---------------- head: fc1(64->128) + gelu + fc2(128->1) ----------------
__global__ void __launch_bounds__(128) k_fc(const float* __restrict__ w1,
        const float* __restrict__ b1, const float* __restrict__ w2,
        const float* __restrict__ b2, float* __restrict__ out, int sel){
    __shared__ float sw1[CC*128];
    __shared__ float sin_[CC];
    __shared__ float spart[4];
    int tid = threadIdx.x;
    for (int j = tid; j < CC*128; j += 128) sw1[j] = w1[j];
    float myb1 = b1[tid];
    float myw2 = w2[tid];
    float b2v  = b2[0];
    const float* h = selbuf(sel);
    __syncthreads();
    int pbase = blockIdx.x * 32;
    for (int p = 0; p < 32; p++){
        int pix = pbase + p;
        int b = pix >> 16, hw = pix & 65535;
        if (tid < 64) sin_[tid] = h[((b*CC + tid) << 16) + hw];
        __syncthreads();
        float s = myb1;
        #pragma unroll 8
        for (int c2 = 0; c2 < CC; c2++) s += sin_[c2] * sw1[c2*128 + tid];
        float v = gelu_exact(s) * myw2;
        #pragma unroll
        for (int off = 16; off > 0; off >>= 1)
            v += __shfl_down_sync(0xffffffffu, v, off);
        if ((tid & 31) == 0) spart[tid >> 5] = v;
        __syncthreads();
        if (tid == 0) out[pix] = spart[0] + spart[1] + spart[2] + spart[3] + b2v;
        __syncthreads();
    }
}

// ---------------- launch ----------------
extern "C" void kernel_launch(void* const* d_in, const int* in_sizes, int n_in,
                              void* d_out, int out_size){
    const float* x     = (const float*)d_in[0];
    const float* fc0_w = (const float*)d_in[1];
    const float* fc0_b = (const float*)d_in[2];
    const float* w1    = (const float*)d_in[3];
    const float* w2    = (const float*)d_in[4];
    const float* chw   = (const float*)d_in[5];
    const float* chb   = (const float*)d_in[6];
    const float* cww   = (const float*)d_in[7];
    const float* cwb   = (const float*)d_in[8];
    const float* pww   = (const float*)d_in[9];
    const float* pwb   = (const float*)d_in[10];
    const float* fc1_w = (const float*)d_in[11];
    const float* fc1_b = (const float*)d_in[12];
    const float* fc2_w = (const float*)d_in[13];
    const float* fc2_b = (const float*)d_in[14];
    float* out = (float*)d_out;

    cudaFuncSetAttribute(k_conv_mma, cudaFuncAttributeMaxDynamicSharedMemorySize, SMEM_CONV);

    k_init_tw<<<1, 256>>>();
    k_merge<<<(NL*9*64*64 + 255)/256, 256>>>(chw, cww, pww, chb, cwb, pwb);
    k_fc0<<<NPIX/256, 256>>>(x, fc0_w, fc0_b);

    int cur = 0;
    for (int l = 0; l < NL; l++){
        int nxt = cur ^ 1;
        k_dftw <<<dim3(8, CC, BB),  256>>>(cur);
        k_dfth <<<dim3(CC, BB),     800>>>();
        k_mix  <<<800,              512>>>(w1, w2, l);
        k_idfth<<<dim3(CC, BB),     256>>>();
        k_conv_mma<<<dim3(2, HH, BB), 512, SMEM_CONV>>>(cur, nxt, l, (l < NL-1) ? 1 : 0);
        cur = nxt;
    }
    k_fc<<<NPIX/32, 128>>>(fc1_w, fc1_b, fc2_w, fc2_b, out, cur);
}

// round 6
// speedup vs baseline: 2.1441x; 1.2166x over previous
#include <cuda_runtime.h>
#include <cuda_bf16.h>
#include <math.h>
#include <stdint.h>

#define BB 8
#define CC 64
#define HH 256
#define WW 256
#define M1 20
#define M2 20
#define NL 4
#define HW 65536
#define NPIX (BB*HH*WW)

// ---------------- static device scratch ----------------
__device__ float  g_bufA[BB*CC*HW];
__device__ float  g_bufB[BB*CC*HW];
__device__ float2 g_yw [BB*CC*HH*M2];
__device__ float2 g_xft[BB*CC*2*M1*M2];
__device__ float2 g_oft[BB*CC*2*M1*M2];
__device__ float2 g_zh [BB*CC*HH*M2];
__device__ float  g_bm [NL*CC];
__device__ float  g_tc [256];
__device__ float  g_ts [256];
// bf16 hi/lo split conv weights: [l][dy][s*3+dx][n*64+ic]
__device__ __nv_bfloat16 g_wbf2[NL][3][6][64*64];
// bf16 hi/lo split DFT-W twiddle matrix: [s][n(48: 20cos,20 -sin,8 zero)][k=256]
__device__ __nv_bfloat16 g_Tbf[2][48][256];
// pre-transposed spectral-mix weights: [l][mode=kxi*20+ky][ii*64+o] (re,im)
__device__ float2 g_wmix[(size_t)NL*800*4096];

__device__ __forceinline__ float* selbuf(int s){ return s ? g_bufB : g_bufA; }
__device__ __forceinline__ float gelu_exact(float x){
    return 0.5f * x * (1.0f + erff(x * 0.7071067811865476f));
}

__device__ __forceinline__ void mma_bf16(float* c, const uint32_t* a, uint32_t b0, uint32_t b1){
    asm volatile("mma.sync.aligned.m16n8k16.row.col.f32.bf16.bf16.f32 "
        "{%0,%1,%2,%3}, {%4,%5,%6,%7}, {%8,%9}, {%0,%1,%2,%3};"
        : "+f"(c[0]), "+f"(c[1]), "+f"(c[2]), "+f"(c[3])
        : "r"(a[0]), "r"(a[1]), "r"(a[2]), "r"(a[3]), "r"(b0), "r"(b1));
}

// ---- smem layout for k_conv_mma ----
#define ICP 72
#define AH_OFF 0                         // bf16 [3][130][ICP] = 56160 B (reused as reduce buf)
#define AL_OFF 56160
#define WB_OFF 112320                    // bf16 [6][64][ICP]  = 55296 B
#define SZ_OFF 167616                    // float2 [64][20]    = 10240 B
#define SMEM_CONV 177856

// ---- smem layout for k_dftw_mma ----
#define DW_AH 0                          // bf16 [128][264] = 67584 B
#define DW_AL 67584
#define DW_BH 135168                     // bf16 [48][264]  = 25344 B
#define DW_BL 160512
#define DW_SMEM 185856

// ---------------- twiddle init ----------------
__global__ void k_init_tw(){
    int i = threadIdx.x;
    const double TWO_PI = 6.283185307179586476925286766559;
    double th = TWO_PI * (double)i / 256.0;
    g_tc[i] = (float)cos(th);
    g_ts[i] = (float)sin(th);
    for (int n = 0; n < 48; n++){
        float v = 0.f;
        if (n < 20)      v =  (float)cos(TWO_PI * (double)((n*i) & 255) / 256.0);
        else if (n < 40) v = -(float)sin(TWO_PI * (double)(((n-20)*i) & 255) / 256.0);
        __nv_bfloat16 hb = __float2bfloat16(v);
        __nv_bfloat16 lb = __float2bfloat16(v - __bfloat162float(hb));
        g_Tbf[0][n][i] = hb;
        g_Tbf[1][n][i] = lb;
    }
}

// ------- merge convh+convw+pw -> bf16 hi/lo split [l][dy][s*3+dx][n][ic] -------
__global__ void k_merge(const float* __restrict__ ch, const float* __restrict__ cw,
                        const float* __restrict__ pw, const float* __restrict__ bh,
                        const float* __restrict__ bw, const float* __restrict__ bp){
    int idx = blockIdx.x * 256 + threadIdx.x;
    const int total = NL*9*64*64;
    if (idx < total){
        int ic = idx & 63;
        int n  = (idx >> 6) & 63;
        int t  = (idx >> 12) % 9;
        int l  = idx / (9*64*64);
        int dy = t / 3, dx = t % 3;
        int src = ((l*CC + n)*CC + ic)*9 + t;
        float v = ch[src] + cw[src];
        if (t == 4) v += pw[(l*CC + n)*CC + ic];
        __nv_bfloat16 hb = __float2bfloat16(v);
        __nv_bfloat16 lb = __float2bfloat16(v - __bfloat162float(hb));
        g_wbf2[l][dy][0*3+dx][n*64+ic] = hb;
        g_wbf2[l][dy][1*3+dx][n*64+ic] = lb;
    }
    if (idx < NL*CC) g_bm[idx] = bh[idx] + bw[idx] + bp[idx];
}

// ------- pre-transpose spectral weights to [l][mode][ii][o] -------
__global__ void k_wprep(const float* __restrict__ w1, const float* __restrict__ w2){
    size_t idx = (size_t)blockIdx.x * 256 + threadIdx.x;
    const size_t total = (size_t)NL*800*4096;
    if (idx >= total) return;
    int o   = idx & 63;
    int ii  = (idx >> 6) & 63;
    int ky  = (int)((idx >> 12) % 20);
    int kxi = (int)((idx / (4096ull*20)) % 40);
    int l   = (int)(idx / (4096ull*800));
    int kxl = (kxi < 20) ? kxi : kxi - 20;
    const float* w = (kxi < 20) ? w1 : w2;
    size_t s = ((((size_t)(l*64 + ii)*64 + o)*20 + kxl)*20 + ky)*2;
    g_wmix[idx] = make_float2(w[s], w[s+1]);
}

// ---------------- fc0 lift ----------------
__global__ void k_fc0(const float* __restrict__ x, const float* __restrict__ w,
                      const float* __restrict__ bias){
    __shared__ float sw[3*CC];
    __shared__ float sb[CC];
    int tid = threadIdx.x;
    if (tid < 3*CC) sw[tid] = w[tid];
    if (tid < CC)   sb[tid] = bias[tid];
    __syncthreads();
    int pix = blockIdx.x * 256 + tid;
    int b  = pix >> 16;
    int hw = pix & 65535;
    float x0 = x[pix*3+0], x1 = x[pix*3+1], x2 = x[pix*3+2];
    float* out = selbuf(0);
    #pragma unroll 8
    for (int c = 0; c < CC; c++){
        float v = x0*sw[c] + x1*sw[64+c] + x2*sw[128+c] + sb[c];
        out[((b*CC + c) << 16) + hw] = v;
    }
}

// ============ DFT along W as tensor-core GEMM: [128 rows x 256] x [256 x 40] ====
__global__ void __launch_bounds__(256) k_dftw_mma(int insel){
    extern __shared__ unsigned char smem[];
    __nv_bfloat16* sAh = (__nv_bfloat16*)(smem + DW_AH);
    __nv_bfloat16* sAl = (__nv_bfloat16*)(smem + DW_AL);
    __nv_bfloat16* sBh = (__nv_bfloat16*)(smem + DW_BH);
    __nv_bfloat16* sBl = (__nv_bfloat16*)(smem + DW_BL);
    int tid = threadIdx.x, wid = tid >> 5, lane = tid & 31;
    int grp = lane >> 2, t2 = (lane & 3) * 2;
    int r0 = blockIdx.x * 128;
    const float* X = selbuf(insel) + (size_t)r0 * 256;

    // stage A (fp32 -> bf16 hi/lo), pairs
    for (int idx = tid; idx < 128*128; idx += 256){
        int r = idx >> 7, k2 = (idx & 127) * 2;
        float2 f = *(const float2*)&X[r*256 + k2];
        __nv_bfloat16 h0 = __float2bfloat16(f.x);
        __nv_bfloat16 h1 = __float2bfloat16(f.y);
        __nv_bfloat16 l0 = __float2bfloat16(f.x - __bfloat162float(h0));
        __nv_bfloat16 l1 = __float2bfloat16(f.y - __bfloat162float(h1));
        uint32_t hp = (uint32_t)*(unsigned short*)&h0 | ((uint32_t)*(unsigned short*)&h1 << 16);
        uint32_t lp = (uint32_t)*(unsigned short*)&l0 | ((uint32_t)*(unsigned short*)&l1 << 16);
        *(uint32_t*)((unsigned char*)sAh + (r*264 + k2)*2) = hp;
        *(uint32_t*)((unsigned char*)sAl + (r*264 + k2)*2) = lp;
    }
    // stage B
    for (int idx = tid; idx < 48*128; idx += 256){
        int n = idx / 128, k2 = (idx % 128) * 2;
        *(uint32_t*)((unsigned char*)sBh + (n*264 + k2)*2) = *(const uint32_t*)&g_Tbf[0][n][k2];
        *(uint32_t*)((unsigned char*)sBl + (n*264 + k2)*2) = *(const uint32_t*)&g_Tbf[1][n][k2];
    }
    __syncthreads();

    float c[5][4];
    #pragma unroll
    for (int nb = 0; nb < 5; nb++)
        #pragma unroll
        for (int j = 0; j < 4; j++) c[nb][j] = 0.f;

    int arow = wid*16 + grp;
    #pragma unroll 4
    for (int kk = 0; kk < 16; kk++){
        int kc = kk*16 + t2;
        uint32_t ah[4], al[4];
        ah[0] = *(uint32_t*)((unsigned char*)sAh + (arow*264 + kc)*2);
        ah[1] = *(uint32_t*)((unsigned char*)sAh + ((arow+8)*264 + kc)*2);
        ah[2] = *(uint32_t*)((unsigned char*)sAh + (arow*264 + kc + 8)*2);
        ah[3] = *(uint32_t*)((unsigned char*)sAh + ((arow+8)*264 + kc + 8)*2);
        al[0] = *(uint32_t*)((unsigned char*)sAl + (arow*264 + kc)*2);
        al[1] = *(uint32_t*)((unsigned char*)sAl + ((arow+8)*264 + kc)*2);
        al[2] = *(uint32_t*)((unsigned char*)sAl + (arow*264 + kc + 8)*2);
        al[3] = *(uint32_t*)((unsigned char*)sAl + ((arow+8)*264 + kc + 8)*2);
        #pragma unroll
        for (int nb = 0; nb < 5; nb++){
            int n = nb*8 + grp;
            uint32_t bh0 = *(uint32_t*)((unsigned char*)sBh + (n*264 + kc)*2);
            uint32_t bh1 = *(uint32_t*)((unsigned char*)sBh + (n*264 + kc + 8)*2);
            uint32_t bl0 = *(uint32_t*)((unsigned char*)sBl + (n*264 + kc)*2);
            uint32_t bl1 = *(uint32_t*)((unsigned char*)sBl + (n*264 + kc + 8)*2);
            mma_bf16(c[nb], ah, bh0, bh1);
            mma_bf16(c[nb], ah, bl0, bl1);
            mma_bf16(c[nb], al, bh0, bh1);
        }
    }

    float* yw = (float*)g_yw;
    #pragma unroll
    for (int nb = 0; nb < 5; nb++){
        #pragma unroll
        for (int j = 0; j < 4; j++){
            int n = nb*8 + t2 + (j & 1);
            if (n >= 40) continue;
            int m = wid*16 + grp + ((j >> 1) << 3);
            int col = (n < 20) ? 2*n : 2*(n-20) + 1;
            yw[(size_t)(r0 + m)*40 + col] = c[nb][j];
        }
    }
}

// ---------------- forward DFT along H: 256 -> 40 modes ----------------
__global__ void k_dfth(){
    __shared__ float2 sy[HH*M2];
    __shared__ float  stc[256], sts[256];
    int tid = threadIdx.x;          // 800
    int c = blockIdx.x, b = blockIdx.y;
    if (tid < 256){ stc[tid] = g_tc[tid]; sts[tid] = g_ts[tid]; }
    const float2* yw = g_yw + (size_t)(b*CC + c)*HH*M2;
    for (int j = tid; j < HH*M2; j += 800) sy[j] = yw[j];
    __syncthreads();
    int kxi = tid / 20, ky = tid % 20;
    int kx  = (kxi < 20) ? kxi : (216 + kxi);
    float re = 0.f, im = 0.f;
    int idx = 0;
    #pragma unroll 4
    for (int h = 0; h < HH; h++){
        float2 y = sy[h*M2 + ky];
        float cth = stc[idx], sth = sts[idx];
        re += y.x*cth + y.y*sth;
        im += y.y*cth - y.x*sth;
        idx = (idx + kx) & 255;
    }
    const float sc = 1.0f/256.0f;
    g_xft[((b*CC + c)*40 + kxi)*M2 + ky] = make_float2(re*sc, im*sc);
}

// ---------------- per-mode complex channel mixing (smem-staged weights) --------
__global__ void __launch_bounds__(512) k_mix(int layer){
    __shared__ float2 sx[BB*CC];
    __shared__ float  sWr[4096], sWi[4096];
    int tid  = threadIdx.x;          // 512
    int mode = blockIdx.x;           // kxi*20+ky
    int kxi = mode / 20, ky = mode % 20;
    const float2* wsrc = g_wmix + ((size_t)layer*800 + mode)*4096;
    for (int j = tid; j < 4096; j += 512){
        float2 w = wsrc[j];
        sWr[j] = w.x; sWi[j] = w.y;
    }
    int b = tid >> 6, i = tid & 63;
    sx[tid] = g_xft[((b*CC + i)*40 + kxi)*M2 + ky];
    __syncthreads();
    int o = i;
    float re = 0.f, im = 0.f;
    #pragma unroll 8
    for (int ii = 0; ii < CC; ii++){
        float2 xv = sx[(b << 6) + ii];
        float wr = sWr[ii*64 + o], wi_ = sWi[ii*64 + o];
        re += xv.x*wr - xv.y*wi_;
        im += xv.x*wi_ + xv.y*wr;
    }
    g_oft[((b*CC + o)*40 + kxi)*M2 + ky] = make_float2(re, im);
}

// ---------------- inverse DFT along H (40 modes -> 256) ------------------------
__global__ void k_idfth(){
    __shared__ float2 so[40*M2];
    __shared__ float  stc[256], sts[256];
    int tid = threadIdx.x;           // 256
    int o = blockIdx.x, b = blockIdx.y;
    stc[tid] = g_tc[tid]; sts[tid] = g_ts[tid];
    const float2* op = g_oft + (size_t)(b*CC + o)*40*M2;
    for (int j = tid; j < 800; j += 256) so[j] = op[j];
    __syncthreads();
    int h = tid;
    float2* zout = g_zh + ((size_t)(b*CC + o)*HH + h)*M2;
    for (int ky = 0; ky < M2; ky++){
        float re = 0.f, im = 0.f;
        #pragma unroll
        for (int kxi = 0; kxi < 40; kxi++){
            int kx  = (kxi < 20) ? kxi : (216 + kxi);
            int idx = (h * kx) & 255;
            float2 ov = so[kxi*M2 + ky];
            float cth = stc[idx], sth = sts[idx];
            re += ov.x*cth - ov.y*sth;
            im += ov.x*sth + ov.y*cth;
        }
        zout[ky] = make_float2(re, im);
    }
}

// ======== mma conv: warp tile 32x32, 2-way K-split, fused irfft-W epilogue =====
__global__ void __launch_bounds__(512) k_conv_mma(int insel, int outsel, int layer, int dogelu){
    extern __shared__ unsigned char smem[];
    __nv_bfloat16* sAh = (__nv_bfloat16*)(smem + AH_OFF);
    __nv_bfloat16* sAl = (__nv_bfloat16*)(smem + AL_OFF);
    __nv_bfloat16* sB  = (__nv_bfloat16*)(smem + WB_OFF);
    float2*        sz  = (float2*)      (smem + SZ_OFF);

    int tid = threadIdx.x, wid = tid >> 5, lane = tid & 31;
    int w0 = blockIdx.x * 128;
    int h  = blockIdx.y;
    int b  = blockIdx.z;
    const float* in = selbuf(insel) + ((size_t)(b*CC) << 16);

    // ---- stage A (3 dy rows, hi/lo split) + spectral rows ----
    #pragma unroll
    for (int dy = 0; dy < 3; dy++){
        int gh = h + dy - 1;
        if (gh < 0 || gh >= HH) continue;
        const float* rp = in + gh*WW;
        for (int idx = tid; idx < 130*64; idx += 512){
            int ic = idx / 130, w = idx % 130;
            int gw = w0 - 1 + w;
            float v = 0.f;
            if (gw >= 0 && gw < WW) v = rp[((size_t)ic << 16) + gw];
            __nv_bfloat16 hb = __float2bfloat16(v);
            __nv_bfloat16 lb = __float2bfloat16(v - __bfloat162float(hb));
            int o = (dy*130 + w)*ICP + ic;
            sAh[o] = hb; sAl[o] = lb;
        }
    }
    for (int idx = tid; idx < 64*20; idx += 512){
        int oc = idx / 20, ky = idx % 20;
        sz[idx] = g_zh[((size_t)(b*CC + oc)*HH + h)*M2 + ky];
    }

    int mq  = wid & 3;               // px quarter (32 px each)
    int nh  = (wid >> 2) & 1;        // oc half
    int ks  = wid >> 3;              // K half
    int grp = lane >> 2;
    int t2  = (lane & 3) * 2;

    float c[2][4][4];
    #pragma unroll
    for (int m2 = 0; m2 < 2; m2++)
        #pragma unroll
        for (int nb = 0; nb < 4; nb++)
            #pragma unroll
            for (int j = 0; j < 4; j++) c[m2][nb][j] = 0.f;

    int row0 = mq*32 + grp;
    for (int dy = 0; dy < 3; dy++){
        int gh = h + dy - 1;
        if (gh < 0 || gh >= HH) continue;
        __syncthreads();
        {
            const __nv_bfloat16* wsrc = &g_wbf2[layer][dy][0][0];
            for (int idx = tid; idx < 6*64*64; idx += 512){
                int ic = idx & 63, n = (idx >> 6) & 63, r = idx >> 12;
                sB[(r*64 + n)*ICP + ic] = wsrc[idx];
            }
        }
        __syncthreads();

        #pragma unroll
        for (int dx = 0; dx < 3; dx++){
            #pragma unroll
            for (int kk2 = 0; kk2 < 2; kk2++){
                int kc = (ks*2 + kk2)*16 + t2;
                #pragma unroll
                for (int m2 = 0; m2 < 2; m2++){
                    int ar = dy*130 + row0 + m2*16 + dx;
                    uint32_t ah[4], al[4];
                    ah[0] = *(const uint32_t*)(sAh + ar*ICP + kc);
                    ah[1] = *(const uint32_t*)(sAh + (ar+8)*ICP + kc);
                    ah[2] = *(const uint32_t*)(sAh + ar*ICP + kc + 8);
                    ah[3] = *(const uint32_t*)(sAh + (ar+8)*ICP + kc + 8);
                    al[0] = *(const uint32_t*)(sAl + ar*ICP + kc);
                    al[1] = *(const uint32_t*)(sAl + (ar+8)*ICP + kc);
                    al[2] = *(const uint32_t*)(sAl + ar*ICP + kc + 8);
                    al[3] = *(const uint32_t*)(sAl + (ar+8)*ICP + kc + 8);
                    #pragma unroll
                    for (int nb = 0; nb < 4; nb++){
                        int n = nh*32 + nb*8 + grp;
                        uint32_t bh0 = *(const uint32_t*)(sB + ((0*3+dx)*64 + n)*ICP + kc);
                        uint32_t bh1 = *(const uint32_t*)(sB + ((0*3+dx)*64 + n)*ICP + kc + 8);
                        uint32_t bl0 = *(const uint32_t*)(sB + ((1*3+dx)*64 + n)*ICP + kc);
                        uint32_t bl1 = *(const uint32_t*)(sB + ((1*3+dx)*64 + n)*ICP + kc + 8);
                        mma_bf16(c[m2][nb], ah, bh0, bh1);
                        mma_bf16(c[m2][nb], ah, bl0, bl1);
                        mma_bf16(c[m2][nb], al, bh0, bh1);
                    }
                }
            }
        }
        __syncthreads();
    }

    // ---- cross-K reduce via smem (reuse A region) ----
    __syncthreads();
    float* red = (float*)(smem + AH_OFF);
    int t = wid & 7;
    if (ks == 1){
        #pragma unroll
        for (int m2 = 0; m2 < 2; m2++)
            #pragma unroll
            for (int nb = 0; nb < 4; nb++)
                #pragma unroll
                for (int j = 0; j < 4; j++){
                    int row = m2*16 + grp + ((j >> 1) << 3);
                    int col = nb*8 + t2 + (j & 1);
                    red[t*1056 + row*33 + col] = c[m2][nb][j];
                }
    }
    __syncthreads();
    if (ks == 0){
        #pragma unroll
        for (int m2 = 0; m2 < 2; m2++)
            #pragma unroll
            for (int nb = 0; nb < 4; nb++)
                #pragma unroll
                for (int j = 0; j < 4; j++){
                    int row = m2*16 + grp + ((j >> 1) << 3);
                    int col = nb*8 + t2 + (j & 1);
                    c[m2][nb][j] += red[t*1056 + row*33 + col];
                }

        float bias[8];
        #pragma unroll
        for (int nb = 0; nb < 4; nb++){
            int oc = nh*32 + nb*8 + t2;
            bias[nb*2+0] = g_bm[layer*CC + oc];
            bias[nb*2+1] = g_bm[layer*CC + oc + 1];
        }
        float* out = selbuf(outsel) + ((size_t)(b*CC) << 16);
        #pragma unroll
        for (int m2 = 0; m2 < 2; m2++){
            #pragma unroll
            for (int jh = 0; jh < 2; jh++){
                int m  = mq*32 + m2*16 + grp + jh*8;
                int wc = w0 + m;
                float c1 = g_tc[wc], s1 = g_ts[wc];
                float acc[8];
                #pragma unroll
                for (int nb = 0; nb < 4; nb++){
                    int oc = nh*32 + nb*8 + t2;
                    acc[nb*2+0] = sz[oc*20].x;
                    acc[nb*2+1] = sz[(oc+1)*20].x;
                }
                float cr = c1, ci = s1;
                for (int ky = 1; ky < 20; ky++){
                    #pragma unroll
                    for (int nb = 0; nb < 4; nb++){
                        int oc = nh*32 + nb*8 + t2;
                        float2 z0 = sz[oc*20 + ky];
                        float2 z1 = sz[(oc+1)*20 + ky];
                        acc[nb*2+0] += 2.f*(z0.x*cr - z0.y*ci);
                        acc[nb*2+1] += 2.f*(z1.x*cr - z1.y*ci);
                    }
                    float nr = cr*c1 - ci*s1;
                    ci = cr*s1 + ci*c1;
                    cr = nr;
                }
                #pragma unroll
                for (int nb = 0; nb < 4; nb++){
                    int oc = nh*32 + nb*8 + t2;
                    #pragma unroll
                    for (int j2 = 0; j2 < 2; j2++){
                        float v = c[m2][nb][jh*2 + j2] + bias[nb*2+j2] + acc[nb*2+j2]*(1.0f/256.0f);
                        if (dogelu) v = gelu_exact(v);
                        out[((size_t)(oc + j2) << 16) + h*WW + wc] = v;
                    }
                }
            }
        }
    }
}

// ---------------- head: fc1 weights in registers + 4-px float4 batching --------
__global__ void __launch_bounds__(128) k_fc(const float* __restrict__ w1,
        const float* __restrict__ b1, const float* __restrict__ w2,
        const float* __restrict__ b2, float* __restrict__ out, int sel){
    __shared__ float4 s4[CC];
    __shared__ float  sp[16];
    int tid = threadIdx.x, wid = tid >> 5, lane = tid & 31;
    float wreg[64];
    #pragma unroll
    for (int c = 0; c < 64; c++) wreg[c] = w1[c*128 + tid];
    float myb1 = b1[tid];
    float myw2 = w2[tid];
    float b2v  = b2[0];
    const float* h = selbuf(sel);
    int pbase = blockIdx.x * 32;
    for (int p4 = 0; p4 < 8; p4++){
        int pix = pbase + p4*4;
        int b = pix >> 16, hw = pix & 65535;
        if (tid < 64) s4[tid] = *(const float4*)&h[((b*CC + tid) << 16) + hw];
        __syncthreads();
        float s0 = myb1, s1 = myb1, s2 = myb1, s3 = myb1;
        #pragma unroll
        for (int c = 0; c < 64; c++){
            float4 x = s4[c];
            float wv = wreg[c];
            s0 += x.x*wv; s1 += x.y*wv; s2 += x.z*wv; s3 += x.w*wv;
        }
        float v0 = gelu_exact(s0) * myw2;
        float v1 = gelu_exact(s1) * myw2;
        float v2 = gelu_exact(s2) * myw2;
        float v3 = gelu_exact(s3) * myw2;
        #pragma unroll
        for (int off = 16; off > 0; off >>= 1){
            v0 += __shfl_down_sync(0xffffffffu, v0, off);
            v1 += __shfl_down_sync(0xffffffffu, v1, off);
            v2 += __shfl_down_sync(0xffffffffu, v2, off);
            v3 += __shfl_down_sync(0xffffffffu, v3, off);
        }
        if (lane == 0){
            sp[wid*4+0] = v0; sp[wid*4+1] = v1; sp[wid*4+2] = v2; sp[wid*4+3] = v3;
        }
        __syncthreads();
        if (tid < 4) out[pix + tid] = sp[tid] + sp[4+tid] + sp[8+tid] + sp[12+tid] + b2v;
        __syncthreads();
    }
}

// ---------------- launch ----------------
extern "C" void kernel_launch(void* const* d_in, const int* in_sizes, int n_in,
                              void* d_out, int out_size){
    const float* x     = (const float*)d_in[0];
    const float* fc0_w = (const float*)d_in[1];
    const float* fc0_b = (const float*)d_in[2];
    const float* w1    = (const float*)d_in[3];
    const float* w2    = (const float*)d_in[4];
    const float* chw   = (const float*)d_in[5];
    const float* chb   = (const float*)d_in[6];
    const float* cww   = (const float*)d_in[7];
    const float* cwb   = (const float*)d_in[8];
    const float* pww   = (const float*)d_in[9];
    const float* pwb   = (const float*)d_in[10];
    const float* fc1_w = (const float*)d_in[11];
    const float* fc1_b = (const float*)d_in[12];
    const float* fc2_w = (const float*)d_in[13];
    const float* fc2_b = (const float*)d_in[14];
    float* out = (float*)d_out;

    cudaFuncSetAttribute(k_conv_mma, cudaFuncAttributeMaxDynamicSharedMemorySize, SMEM_CONV);
    cudaFuncSetAttribute(k_dftw_mma, cudaFuncAttributeMaxDynamicSharedMemorySize, DW_SMEM);

    k_init_tw<<<1, 256>>>();
    k_merge<<<(NL*9*64*64 + 255)/256, 256>>>(chw, cww, pww, chb, cwb, pwb);
    k_wprep<<<(int)(((size_t)NL*800*4096 + 255)/256), 256>>>(w1, w2);
    k_fc0<<<NPIX/256, 256>>>(x, fc0_w, fc0_b);

    int cur = 0;
    for (int l = 0; l < NL; l++){
        int nxt = cur ^ 1;
        k_dftw_mma<<<1024, 256, DW_SMEM>>>(cur);
        k_dfth <<<dim3(CC, BB), 800>>>();
        k_mix  <<<800, 512>>>(l);
        k_idfth<<<dim3(CC, BB), 256>>>();
        k_conv_mma<<<dim3(2, HH, BB), 512, SMEM_CONV>>>(cur, nxt, l, (l < NL-1) ? 1 : 0);
        cur = nxt;
    }
    k_fc<<<NPIX/32, 128>>>(fc1_w, fc1_b, fc2_w, fc2_b, out, cur);
}